// round 1
// baseline (speedup 1.0000x reference)
#include <cuda_runtime.h>

#define T_STEPS 2048
#define BATCH   2048
#define HID     32

typedef unsigned long long u64;

// ---- packed f32x2 helpers (sm_100a+) ----
__device__ __forceinline__ u64 ffma2(u64 a, u64 b, u64 c) {
    u64 d;
    asm("fma.rn.f32x2 %0, %1, %2, %3;" : "=l"(d) : "l"(a), "l"(b), "l"(c));
    return d;
}
__device__ __forceinline__ u64 pack2(float lo, float hi) {
    u64 d;
    asm("mov.b64 %0, {%1, %2};" : "=l"(d) : "f"(lo), "f"(hi));
    return d;
}
__device__ __forceinline__ void unpack2(u64 v, float& lo, float& hi) {
    asm("mov.b64 {%0, %1}, %2;" : "=f"(lo), "=f"(hi) : "l"(v));
}
// ---- fast activations ----
__device__ __forceinline__ float ex2f(float x) {
    float y; asm("ex2.approx.f32 %0, %1;" : "=f"(y) : "f"(x)); return y;
}
__device__ __forceinline__ float rcpf(float x) {
    float y; asm("rcp.approx.f32 %0, %1;" : "=f"(y) : "f"(x)); return y;
}
// sigmoid(x) = 1/(1+2^(-x*log2e))
__device__ __forceinline__ float sigm(float x) {
    return rcpf(1.0f + ex2f(x * -1.4426950408889634f));
}
// tanh(x) = 2/(1+e^(-2x)) - 1
__device__ __forceinline__ float tanh_(float x) {
    return fmaf(2.0f, rcpf(1.0f + ex2f(x * -2.8853900817779268f)), -1.0f);
}

__global__ void __launch_bounds__(128, 2) lstm_kernel(
    const float* __restrict__ x,      // [T, B, 1]
    const float* __restrict__ W_ih,   // [4H, 1]
    const float* __restrict__ W_hh,   // [4H, H]
    const float* __restrict__ b_ih,   // [4H]
    const float* __restrict__ b_hh,   // [4H]
    const float* __restrict__ W_out,  // [1, H]
    const float* __restrict__ b_out,  // [1]
    float* __restrict__ out,          // [T*B] outs, then [B*H] hT, then [B*H] cT
    int out_size)
{
    const int lane = threadIdx.x & 31;
    const int wid  = threadIdx.x >> 5;
    const int w    = blockIdx.x * 4 + wid;   // 0..1023
    const int b0   = 2 * w;                  // batch pair (b0, b0+1)

    // Per-lane weights: lane handles hidden index j=lane; gate g uses row g*32+j.
    // W_hh row packed as 16 f32x2 pairs (k-pairs, consecutive in memory).
    u64 w2[4][16];
    u64 wih2[4], bias2[4];
    #pragma unroll
    for (int g = 0; g < 4; g++) {
        const int row = g * 32 + lane;
        const float* wr = W_hh + row * HID;
        #pragma unroll
        for (int p = 0; p < 16; p++)
            w2[g][p] = *reinterpret_cast<const u64*>(wr + 2 * p);
        wih2[g]  = pack2(W_ih[row], 0.0f);
        bias2[g] = pack2(b_ih[row] + b_hh[row], 0.0f);
    }
    const float wout = W_out[lane];
    const float bout = b_out[0];

    // h broadcast staging: [warp][double-buffer][batch][hidden]
    __shared__ __align__(16) float sh[4][2][2][32];

    float h0 = 0.0f, c0 = 0.0f, h1 = 0.0f, c1 = 0.0f;

    // prefetch x for t=0 (pair b0,b0+1 -> one LDG.64)
    float2 xv = *reinterpret_cast<const float2*>(x + b0);

    #pragma unroll 1
    for (int t = 0; t < T_STEPS; t++) {
        const int buf = t & 1;
        // publish previous h
        sh[wid][buf][0][lane] = h0;
        sh[wid][buf][1][lane] = h1;

        // prefetch next x early
        const int tn = (t + 1 < T_STEPS) ? (t + 1) : t;
        float2 xnext = *reinterpret_cast<const float2*>(x + (size_t)tn * BATCH + b0);

        // init gate accumulators with x contribution + bias (lo half), hi half 0
        u64 acc0[4], acc1[4];
        {
            u64 xp0 = pack2(xv.x, 0.0f);
            u64 xp1 = pack2(xv.y, 0.0f);
            #pragma unroll
            for (int g = 0; g < 4; g++) {
                acc0[g] = ffma2(xp0, wih2[g], bias2[g]);
                acc1[g] = ffma2(xp1, wih2[g], bias2[g]);
            }
        }

        __syncwarp();

        // recurrent matvec: 8 chains (2 batches x 4 gates), 128 FFMA2 total
        const double2* hp0 = reinterpret_cast<const double2*>(sh[wid][buf][0]);
        const double2* hp1 = reinterpret_cast<const double2*>(sh[wid][buf][1]);
        #pragma unroll
        for (int q = 0; q < 8; q++) {
            double2 v0 = hp0[q];             // LDS.128 broadcast
            double2 v1 = hp1[q];
            u64 p00 = __double_as_longlong(v0.x), p01 = __double_as_longlong(v0.y);
            u64 p10 = __double_as_longlong(v1.x), p11 = __double_as_longlong(v1.y);
            #pragma unroll
            for (int g = 0; g < 4; g++) {
                acc0[g] = ffma2(p00, w2[g][2 * q], acc0[g]);
                acc1[g] = ffma2(p10, w2[g][2 * q], acc1[g]);
            }
            #pragma unroll
            for (int g = 0; g < 4; g++) {
                acc0[g] = ffma2(p01, w2[g][2 * q + 1], acc0[g]);
                acc1[g] = ffma2(p11, w2[g][2 * q + 1], acc1[g]);
            }
        }

        // horizontal add + activations (PyTorch gate order i,f,g,o)
        float v0[4], v1[4];
        #pragma unroll
        for (int g = 0; g < 4; g++) {
            float lo, hi;
            unpack2(acc0[g], lo, hi); v0[g] = lo + hi;
            unpack2(acc1[g], lo, hi); v1[g] = lo + hi;
        }
        float i0 = sigm(v0[0]), f0 = sigm(v0[1]), g0 = tanh_(v0[2]), o0 = sigm(v0[3]);
        float i1 = sigm(v1[0]), f1 = sigm(v1[1]), g1 = tanh_(v1[2]), o1 = sigm(v1[3]);

        c0 = fmaf(f0, c0, i0 * g0);
        c1 = fmaf(f1, c1, i1 * g1);
        h0 = o0 * tanh_(c0);
        h1 = o1 * tanh_(c1);

        // output projection: warp-reduce h . W_out
        float r0 = h0 * wout;
        float r1 = h1 * wout;
        #pragma unroll
        for (int off = 16; off; off >>= 1) {
            r0 += __shfl_xor_sync(0xffffffffu, r0, off);
            r1 += __shfl_xor_sync(0xffffffffu, r1, off);
        }
        if (lane == 0) {
            out[(size_t)t * BATCH + b0]     = r0 + bout;
            out[(size_t)t * BATCH + b0 + 1] = r1 + bout;
        }

        xv = xnext;
    }

    // final state (hT, cT), each [B, H], appended after outs
    if (out_size >= T_STEPS * BATCH + 2 * BATCH * HID) {
        float* hT = out + (size_t)T_STEPS * BATCH;
        float* cT = hT + BATCH * HID;
        hT[(size_t)b0 * HID + lane]       = h0;
        hT[(size_t)(b0 + 1) * HID + lane] = h1;
        cT[(size_t)b0 * HID + lane]       = c0;
        cT[(size_t)(b0 + 1) * HID + lane] = c1;
    }
}

extern "C" void kernel_launch(void* const* d_in, const int* in_sizes, int n_in,
                              void* d_out, int out_size) {
    const float* x     = (const float*)d_in[0];
    const float* W_ih  = (const float*)d_in[1];
    const float* W_hh  = (const float*)d_in[2];
    const float* b_ih  = (const float*)d_in[3];
    const float* b_hh  = (const float*)d_in[4];
    const float* W_out = (const float*)d_in[5];
    const float* b_out = (const float*)d_in[6];
    float* out = (float*)d_out;

    // 1024 warps (2 batch elems each) = 256 CTAs of 128 threads; one wave at 2 CTA/SM
    lstm_kernel<<<256, 128>>>(x, W_ih, W_hh, b_ih, b_hh, W_out, b_out, out, out_size);
}

// round 2
// speedup vs baseline: 1.8438x; 1.8438x over previous
#include <cuda_runtime.h>

#define T_STEPS 2048
#define BATCH   2048
#define HID     32

typedef unsigned long long u64;

// ---- packed f32x2 helpers (sm_100a+) ----
__device__ __forceinline__ u64 ffma2(u64 a, u64 b, u64 c) {
    u64 d;
    asm("fma.rn.f32x2 %0, %1, %2, %3;" : "=l"(d) : "l"(a), "l"(b), "l"(c));
    return d;
}
__device__ __forceinline__ u64 pack2(float lo, float hi) {
    u64 d;
    asm("mov.b64 %0, {%1, %2};" : "=l"(d) : "f"(lo), "f"(hi));
    return d;
}
__device__ __forceinline__ void unpack2(u64 v, float& lo, float& hi) {
    asm("mov.b64 {%0, %1}, %2;" : "=f"(lo), "=f"(hi) : "l"(v));
}
// ---- fast activations (ex2/rcp: ~2^-22, effectively exact for 1e-3 tol) ----
__device__ __forceinline__ float ex2f(float x) {
    float y; asm("ex2.approx.f32 %0, %1;" : "=f"(y) : "f"(x)); return y;
}
__device__ __forceinline__ float rcpf(float x) {
    float y; asm("rcp.approx.f32 %0, %1;" : "=f"(y) : "f"(x)); return y;
}
__device__ __forceinline__ float sigm(float x) {
    return rcpf(1.0f + ex2f(x * -1.4426950408889634f));
}
__device__ __forceinline__ float tanh_(float x) {
    return fmaf(2.0f, rcpf(1.0f + ex2f(x * -2.8853900817779268f)), -1.0f);
}

__global__ void __launch_bounds__(128, 2) lstm_kernel(
    const float* __restrict__ x,      // [T, B, 1]
    const float* __restrict__ W_ih,   // [4H, 1]
    const float* __restrict__ W_hh,   // [4H, H]
    const float* __restrict__ b_ih,   // [4H]
    const float* __restrict__ b_hh,   // [4H]
    const float* __restrict__ W_out,  // [1, H]
    const float* __restrict__ b_out,  // [1]
    float* __restrict__ out,          // [T*B] outs, then [B*H] hT, then [B*H] cT
    int out_size)
{
    const int lane = threadIdx.x & 31;
    const int wid  = threadIdx.x >> 5;
    const int w    = blockIdx.x * 4 + wid;   // 0..1023
    const int b0   = 2 * w;                  // batch pair (b0, b0+1)

    // Per-lane weights: lane handles hidden index j=lane; gate g uses row g*32+j.
    u64 w2[4][16];
    float wih[4], bias[4];
    #pragma unroll
    for (int g = 0; g < 4; g++) {
        const int row = g * 32 + lane;
        const float* wr = W_hh + row * HID;
        #pragma unroll
        for (int p = 0; p < 16; p++)
            w2[g][p] = *reinterpret_cast<const u64*>(wr + 2 * p);
        wih[g]  = W_ih[row];
        bias[g] = b_ih[row] + b_hh[row];
    }
    const float wout = W_out[lane];
    const float bout = b_out[0];

    // h broadcast staging: [warp][double-buffer][batch][hidden]
    __shared__ __align__(16) float sh[4][2][2][32];

    float h0 = 0.0f, c0 = 0.0f, h1 = 0.0f, c1 = 0.0f;
    float rp0 = 0.0f, rp1 = 0.0f;             // deferred output partials (step t-1)

    const float* xp = x + b0;                 // x[t, b0]
    float2 xv = *reinterpret_cast<const float2*>(xp);
    float* outp = out + b0;                   // advanced each stored step

    #pragma unroll 1
    for (int t = 0; t < T_STEPS; t++) {
        const int buf = t & 1;
        // publish previous h
        sh[wid][buf][0][lane] = h0;
        sh[wid][buf][1][lane] = h1;

        // clamped prefetch of next x (SEL, no branch)
        const float* xpn = (t < T_STEPS - 1) ? (xp + BATCH) : xp;
        float2 xnext = *reinterpret_cast<const float2*>(xpn);
        xp = xpn;

        // init gate accumulators: lo = x*wih + bias, hi = 0
        u64 acc0[4], acc1[4];
        #pragma unroll
        for (int g = 0; g < 4; g++) {
            acc0[g] = pack2(fmaf(xv.x, wih[g], bias[g]), 0.0f);
            acc1[g] = pack2(fmaf(xv.y, wih[g], bias[g]), 0.0f);
        }

        __syncwarp();

        // ---- deferred reduction of previous step's output partials ----
        // The 5-deep SHFL chain (lat ~26 each) is fully hidden under the
        // independent FFMA2 block below (ptxas interleaves within the block).
        float r0 = rp0, r1 = rp1;
        #pragma unroll
        for (int off = 16; off; off >>= 1) {
            r0 += __shfl_xor_sync(0xffffffffu, r0, off);
            r1 += __shfl_xor_sync(0xffffffffu, r1, off);
        }

        // recurrent matvec: 8 chains (2 batches x 4 gates), 128 FFMA2 total
        const double2* hp0 = reinterpret_cast<const double2*>(sh[wid][buf][0]);
        const double2* hp1 = reinterpret_cast<const double2*>(sh[wid][buf][1]);
        #pragma unroll
        for (int q = 0; q < 8; q++) {
            double2 v0 = hp0[q];             // LDS.128 broadcast
            double2 v1 = hp1[q];
            u64 p00 = __double_as_longlong(v0.x), p01 = __double_as_longlong(v0.y);
            u64 p10 = __double_as_longlong(v1.x), p11 = __double_as_longlong(v1.y);
            #pragma unroll
            for (int g = 0; g < 4; g++) {
                acc0[g] = ffma2(p00, w2[g][2 * q], acc0[g]);
                acc1[g] = ffma2(p10, w2[g][2 * q], acc1[g]);
            }
            #pragma unroll
            for (int g = 0; g < 4; g++) {
                acc0[g] = ffma2(p01, w2[g][2 * q + 1], acc0[g]);
                acc1[g] = ffma2(p11, w2[g][2 * q + 1], acc1[g]);
            }
        }

        // store out[t-1] (reduction finished long ago; fire-and-forget STG.64)
        if (t > 0) {
            if (lane == 0)
                *reinterpret_cast<float2*>(outp) = make_float2(r0 + bout, r1 + bout);
            outp += BATCH;
        }

        // horizontal add + activations (PyTorch gate order i,f,g,o)
        float v0[4], v1[4];
        #pragma unroll
        for (int g = 0; g < 4; g++) {
            float lo, hi;
            unpack2(acc0[g], lo, hi); v0[g] = lo + hi;
            unpack2(acc1[g], lo, hi); v1[g] = lo + hi;
        }
        float i0 = sigm(v0[0]), f0 = sigm(v0[1]), g0 = tanh_(v0[2]), o0 = sigm(v0[3]);
        float i1 = sigm(v1[0]), f1 = sigm(v1[1]), g1 = tanh_(v1[2]), o1 = sigm(v1[3]);

        c0 = fmaf(f0, c0, i0 * g0);
        c1 = fmaf(f1, c1, i1 * g1);
        h0 = o0 * tanh_(c0);
        h1 = o1 * tanh_(c1);

        // new output partials (reduced next iteration)
        rp0 = h0 * wout;
        rp1 = h1 * wout;

        xv = xnext;
    }

    // epilogue: reduce final step's partials -> out[T-1]
    {
        float r0 = rp0, r1 = rp1;
        #pragma unroll
        for (int off = 16; off; off >>= 1) {
            r0 += __shfl_xor_sync(0xffffffffu, r0, off);
            r1 += __shfl_xor_sync(0xffffffffu, r1, off);
        }
        if (lane == 0)
            *reinterpret_cast<float2*>(outp) = make_float2(r0 + bout, r1 + bout);
    }

    // final state (hT, cT), each [B, H], appended after outs
    if (out_size >= T_STEPS * BATCH + 2 * BATCH * HID) {
        float* hT = out + (size_t)T_STEPS * BATCH;
        float* cT = hT + BATCH * HID;
        hT[(size_t)b0 * HID + lane]       = h0;
        hT[(size_t)(b0 + 1) * HID + lane] = h1;
        cT[(size_t)b0 * HID + lane]       = c0;
        cT[(size_t)(b0 + 1) * HID + lane] = c1;
    }
}

extern "C" void kernel_launch(void* const* d_in, const int* in_sizes, int n_in,
                              void* d_out, int out_size) {
    const float* x     = (const float*)d_in[0];
    const float* W_ih  = (const float*)d_in[1];
    const float* W_hh  = (const float*)d_in[2];
    const float* b_ih  = (const float*)d_in[3];
    const float* b_hh  = (const float*)d_in[4];
    const float* W_out = (const float*)d_in[5];
    const float* b_out = (const float*)d_in[6];
    float* out = (float*)d_out;

    // 1024 warps (2 batch elems each) = 256 CTAs of 128 threads
    lstm_kernel<<<256, 128>>>(x, W_ih, W_hh, b_ih, b_hh, W_out, b_out, out, out_size);
}